// round 1
// baseline (speedup 1.0000x reference)
#include <cuda_runtime.h>

#define HALFW 6
#define MAXC  63
#define NK    21
#define NB    64
#define NC    256
#define NH    64
#define NW    64
#define HW    (NH * NW)

// Scratch (allocation-free rule: __device__ globals)
__device__ float g_fm[2][NB][NH][NW];   // channel means, 2 MiB
__device__ float g_fea[2][NK];          // per-keypoint batch-mean box means

// ---------------------------------------------------------------------------
// Kernel 1: fm[t][b][h][w] = (1/256) * sum_c f[b][c][h][w]
// float4 vectorized, coalesced; each thread owns 4 spatial cols, loops over C.
// grid = (HW/(256*4), B, 2), block = 256
// ---------------------------------------------------------------------------
__global__ void __launch_bounds__(256) chan_mean_kernel(
    const float* __restrict__ f1, const float* __restrict__ f2)
{
    const int t   = blockIdx.z;
    const int b   = blockIdx.y;
    const int hw4 = blockIdx.x * blockDim.x + threadIdx.x;   // 0..1023

    const float4* __restrict__ f4 =
        reinterpret_cast<const float4*>(t == 0 ? f1 : f2);
    const float4* __restrict__ p = f4 + (size_t)b * NC * (HW / 4) + hw4;

    float4 acc = make_float4(0.f, 0.f, 0.f, 0.f);
#pragma unroll 8
    for (int c = 0; c < NC; ++c) {
        float4 v = p[(size_t)c * (HW / 4)];
        acc.x += v.x; acc.y += v.y; acc.z += v.z; acc.w += v.w;
    }
    const float s = 1.0f / (float)NC;
    float4 o = make_float4(acc.x * s, acc.y * s, acc.z * s, acc.w * s);
    reinterpret_cast<float4*>(&g_fm[t][b][0][0])[hw4] = o;
}

// ---------------------------------------------------------------------------
// Kernel 2: per (tensor, keypoint): mean over batch of per-box mean.
// grid = 42 blocks, block = 512 threads (64 batches x 8 threads per box).
// All g_fm reads are L2/L1 hits (2 MiB working set).
// ---------------------------------------------------------------------------
__global__ void __launch_bounds__(512) box_mean_kernel(
    const int* __restrict__ pre1, const int* __restrict__ pre2)
{
    const int t   = blockIdx.x / NK;
    const int k   = blockIdx.x % NK;
    const int tid = threadIdx.x;
    const int b   = tid >> 3;
    const int j   = tid & 7;

    const int* __restrict__ pre = (t == 0) ? pre1 : pre2;
    const int x = pre[(b * NK + k) * 2 + 0];
    const int y = pre[(b * NK + k) * 2 + 1];

    // x masks rows (H), y masks cols (W) — matches the reference exactly.
    const int left  = max(x - HALFW, 0);
    const int right = min(x + HALFW, MAXC);   // exclusive
    const int down  = max(y - HALFW, 0);
    const int up    = min(y + HALFW, MAXC);   // exclusive

    const int nh = right - left;
    const int nw = up - down;
    const int ncell = nh * nw;                // == cnt, always >= 36

    float s = 0.f;
    for (int i = j; i < ncell; i += 8) {
        const int h = left + i / nw;
        const int w = down + i % nw;
        s += g_fm[t][b][h][w];
    }
    s *= 1.0f / (float)ncell;                 // box mean contribution

    __shared__ float red[512];
    red[tid] = s;
    __syncthreads();
#pragma unroll
    for (int off = 256; off > 0; off >>= 1) {
        if (tid < off) red[tid] += red[tid + off];
        __syncthreads();
    }
    if (tid == 0) g_fea[t][k] = red[0] * (1.0f / (float)NB);
}

// ---------------------------------------------------------------------------
// Kernel 3: loss = mean_k (fea1[k] - 0.999 * fea2[k])^2
// ---------------------------------------------------------------------------
__global__ void loss_kernel(float* __restrict__ out)
{
    const int k = threadIdx.x;   // 32 threads, one warp
    float d2 = 0.f;
    if (k < NK) {
        const float d = g_fea[0][k] - 0.999f * g_fea[1][k];
        d2 = d * d;
    }
#pragma unroll
    for (int off = 16; off > 0; off >>= 1)
        d2 += __shfl_down_sync(0xffffffffu, d2, off);
    if (k == 0) out[0] = d2 * (1.0f / (float)NK);
}

extern "C" void kernel_launch(void* const* d_in, const int* in_sizes, int n_in,
                              void* d_out, int out_size)
{
    const float* f1   = (const float*)d_in[0];
    const float* f2   = (const float*)d_in[1];
    const int*   pre1 = (const int*)d_in[2];
    const int*   pre2 = (const int*)d_in[3];

    chan_mean_kernel<<<dim3(HW / (256 * 4), NB, 2), 256>>>(f1, f2);
    box_mean_kernel<<<2 * NK, 512>>>(pre1, pre2);
    loss_kernel<<<1, 32>>>((float*)d_out);
}